// round 17
// baseline (speedup 1.0000x reference)
#include <cuda_runtime.h>
#include <cuda_fp16.h>
#include <cstdint>
#include <cstddef>

// ---------------------------------------------------------------------------
// LSTM cell, B=65536, I=H=256. Baseline-PTX path (no tcgen05 on this
// harness's ptxas target): cp.async + ldmatrix + mma.sync.m16n8k16.f16 acc.
//
// Pass 1: [x|h] -> fp16 scratch (B x 512), [Wi|Wh] -> fp16 (1024 x 512).
// Pass 2: gates = XH @ W^T at R15's pareto-optimal geometry (24 warps/SM:
//         3 CTAs x 8 warps, CTA tile M=128 x N=128, 32x64 warp tiles), but
//         the per-chunk __syncthreads/wait_group rendezvous is replaced by
//         an mbarrier producer/consumer pipeline: K-chunk 32 (16KB stages,
//         64B rows, SW64 swizzle), NSTG=4, per-stage full(count 256, armed
//         via cp.async.mbarrier.arrive.noinc) + empty(count 8, lane-0
//         arrive). Warps drift up to 3 chunks -> fill latency is hidden by
//         decoupling rather than by more warps (L1 ceiling found in R16).
// Output: d_out[0 : B*H] = h_new, d_out[B*H : 2*B*H] = c_new.
// ---------------------------------------------------------------------------

#define BATCH   65536
#define HID     256
#define KDIM    512
#define M_TILE  128
#define KC      32            // halves per K chunk = 64 bytes per row
#define NCHUNK  16            // 512 / 32
#define NSTG    4
#define STAGE_A 8192          // 128 rows * 64B
#define STAGE_B 8192          // 128 rows * 64B
#define STAGE_BYTES 16384
#define DYN_SMEM (NSTG * STAGE_BYTES)   // 65536 -> 3 CTAs/SM
#define SGS     66            // half2 stride for epilogue staging (64 + pad)

// fp16 scratch (module-static device memory; no runtime allocation)
__device__ __half xh16g[(size_t)BATCH * KDIM];   // 64 MB
__device__ __half w16g[1024 * KDIM];             // 1 MB

// ---------------- helpers ----------------

__device__ __forceinline__ uint32_t swz64(uint32_t o) {
    return o ^ ((o >> 3) & 0x30);          // SW64: xor bits[4:5] with bits[7:8]
}

#define CP_ASYNC16(dst, src) \
    asm volatile("cp.async.cg.shared.global [%0], [%1], 16;" \
                 :: "r"(dst), "l"(src) : "memory")

#define CPASYNC_MBAR(addr) \
    asm volatile("cp.async.mbarrier.arrive.noinc.shared::cta.b64 [%0];" \
                 :: "r"(addr) : "memory")

#define MBAR_INIT(addr, cnt) \
    asm volatile("mbarrier.init.shared::cta.b64 [%0], %1;" \
                 :: "r"(addr), "r"(cnt) : "memory")

#define MBAR_ARRIVE(addr) \
    asm volatile("mbarrier.arrive.shared::cta.b64 _, [%0];" \
                 :: "r"(addr) : "memory")

#define MBAR_WAIT(addr, ph) do {                                              \
    asm volatile(                                                             \
        "{\n\t"                                                               \
        ".reg .pred P;\n\t"                                                   \
        "WL_%=:\n\t"                                                          \
        "mbarrier.try_wait.parity.acquire.cta.shared::cta.b64 P, [%0], %1, 0x989680;\n\t" \
        "@P bra.uni WD_%=;\n\t"                                               \
        "bra.uni WL_%=;\n\t"                                                  \
        "WD_%=:\n\t"                                                          \
        "}"                                                                   \
        :: "r"(addr), "r"(ph) : "memory");                                    \
} while (0)

#define LDSM4(R, addr) \
    asm volatile("ldmatrix.sync.aligned.m8n8.x4.shared.b16 {%0,%1,%2,%3}, [%4];" \
                 : "=r"((R)[0]), "=r"((R)[1]), "=r"((R)[2]), "=r"((R)[3]) \
                 : "r"(addr))

// fp16-accumulate MMA, chained (C = D). Internal dot product fp32, one
// rounding per instruction.
#define MMA16816H(d, a, b0, b1) \
    asm volatile("mma.sync.aligned.m16n8k16.row.col.f16.f16.f16.f16 " \
                 "{%0,%1},{%2,%3,%4,%5},{%6,%7},{%0,%1};" \
                 : "+r"((d)[0]), "+r"((d)[1]) \
                 : "r"((a)[0]), "r"((a)[1]), "r"((a)[2]), "r"((a)[3]), \
                   "r"(b0), "r"(b1))

__device__ __forceinline__ float sigf(float x) {
    return __fdividef(1.0f, 1.0f + __expf(-x));
}
__device__ __forceinline__ float tanhf_fast(float x) {
    return 1.0f - __fdividef(2.0f, 1.0f + __expf(2.0f * x));
}

// ---------------- pass 1: fp32 -> fp16 concat convert ----------------
// rows [0, BATCH):            xh16g[r*512+k] = k<256 ? x[r,k] : h[r,k-256]
// rows [BATCH, BATCH+1024):   w16g [r*512+k] = k<256 ? Wi[r,k] : Wh[r,k-256]

__global__ void __launch_bounds__(256) conv_all_kernel(const float* __restrict__ x,
                                                       const float* __restrict__ h,
                                                       const float* __restrict__ Wi,
                                                       const float* __restrict__ Wh)
{
    size_t i = ((size_t)blockIdx.x * blockDim.x + threadIdx.x) * 8;
    if (i >= (size_t)(BATCH + 1024) * KDIM) return;
    int r = (int)(i >> 9);
    int k = (int)(i & 511);
    const float* A;
    const float* Bm;
    __half* dst;
    size_t row;
    if (r < BATCH) { A = x;  Bm = h;  dst = xh16g; row = (size_t)r; }
    else           { A = Wi; Bm = Wh; dst = w16g;  row = (size_t)(r - BATCH); }
    const float* s = (k < 256) ? (A + row * 256 + k) : (Bm + row * 256 + (k - 256));
    float4 f0 = ((const float4*)s)[0];
    float4 f1 = ((const float4*)s)[1];
    __half2 h0 = __floats2half2_rn(f0.x, f0.y);
    __half2 h1 = __floats2half2_rn(f0.z, f0.w);
    __half2 h2 = __floats2half2_rn(f1.x, f1.y);
    __half2 h3 = __floats2half2_rn(f1.z, f1.w);
    uint4 v;
    v.x = *(uint32_t*)&h0; v.y = *(uint32_t*)&h1;
    v.z = *(uint32_t*)&h2; v.w = *(uint32_t*)&h3;
    *(uint4*)(dst + row * KDIM + k) = v;
}

// ---------------- pass 2: GEMM + LSTM ----------------
// B tile rows: tile row r (0..127) -> gate g = r>>5, jj = r&31,
//              weight row g*256 + jbase + jj.

// One thread's slice of a 16KB stage fill: 4 x 16B cp.async + mbarrier arm.
__device__ __forceinline__ void issue_stage(uint32_t smb, int stage, int kc,
                                            int tid, int mrow, int jbase,
                                            uint32_t full_addr)
{
    const uint32_t abase = smb + stage * STAGE_BYTES;
    const uint32_t bbase = abase + STAGE_A;
    #pragma unroll
    for (int j = 0; j < 4; ++j) {
        const int slot = tid + j * 256;          // 0..1023
        if (slot < 512) {                        // A: 128 rows x 4 segs of 16B
            const int row = slot >> 2, seg = slot & 3;
            const uint32_t d = abase + swz64(row * 64 + seg * 16);
            const __half* src = xh16g + ((size_t)(mrow + row) << 9) + kc * KC + seg * 8;
            CP_ASYNC16(d, src);
        } else {                                 // B: 128 rows x 4 segs
            const int t = slot - 512;
            const int row = t >> 2, seg = t & 3;
            const int wrow = ((row >> 5) << 8) + jbase + (row & 31);
            const uint32_t d = bbase + swz64(row * 64 + seg * 16);
            const __half* src = w16g + ((size_t)wrow << 9) + kc * KC + seg * 8;
            CP_ASYNC16(d, src);
        }
    }
    CPASYNC_MBAR(full_addr);   // arrive when THIS thread's cp.asyncs land
}

extern "C" __global__ void __launch_bounds__(256, 3)
lstm_gemm_kernel(const float* __restrict__ c_in,
                 const float* __restrict__ bi,
                 const float* __restrict__ bh,
                 float* __restrict__ h_out,
                 float* __restrict__ c_out)
{
    extern __shared__ __align__(1024) char dynsmem[];
    __shared__ float sbias[128];
    __shared__ uint64_t mb_full[NSTG];
    __shared__ uint64_t mb_empty[NSTG];

    const int tid  = threadIdx.x;
    const int lane = tid & 31;
    const int wid  = tid >> 5;
    const int wm   = wid >> 1;           // warp row 0..3 (32 m-rows each)
    const int wn   = wid & 1;            // warp col 0..1 (64 tile-cols each)

    const int m_tile = (int)(blockIdx.x >> 3);
    const int jslice = (int)(blockIdx.x & 7);
    const int mrow   = m_tile * M_TILE;
    const int jbase  = jslice * 32;

    const uint32_t smb = (uint32_t)__cvta_generic_to_shared(dynsmem);
    uint32_t fullA[NSTG], emptyA[NSTG];
    #pragma unroll
    for (int s = 0; s < NSTG; ++s) {
        fullA[s]  = (uint32_t)__cvta_generic_to_shared(&mb_full[s]);
        emptyA[s] = (uint32_t)__cvta_generic_to_shared(&mb_empty[s]);
    }

    if (tid == 0) {
        #pragma unroll
        for (int s = 0; s < NSTG; ++s) {
            MBAR_INIT(fullA[s], 256);    // one arrive per thread (cp.async)
            MBAR_INIT(emptyA[s], 8);     // one arrive per warp (lane 0)
        }
    }
    // bias sums for tile cols tc = g*32 + jj  ->  actual col g*256+jbase+jj
    if (tid < 128) {
        const int g = tid >> 5, jj = tid & 31;
        sbias[tid] = bi[g * 256 + jbase + jj] + bh[g * 256 + jbase + jj];
    }
    __syncthreads();   // barriers initialized before any use

    // f16x2 master accumulators (32 chained MMA roundings, as in R15).
    uint32_t hmast[2][8][2];
    #pragma unroll
    for (int mt = 0; mt < 2; ++mt)
        #pragma unroll
        for (int nt = 0; nt < 8; ++nt) {
            hmast[mt][nt][0] = 0u;
            hmast[mt][nt][1] = 0u;
        }

    // ldmatrix per-lane offsets (64B rows, SW64 swizzle)
    const int a_row0 = wm * 32 + (lane & 15);
    const int a_koff = (lane >> 4) * 16;
    const int b_rowc = wn * 64 + ((lane >> 4) << 3) + (lane & 7);
    const int b_koff = ((lane >> 3) & 1) * 16;

    // prologue: fill stages 0..2 with chunks 0..2 (no empty wait needed)
    #pragma unroll
    for (int c = 0; c < NSTG - 1; ++c)
        issue_stage(smb, c, c, tid, mrow, jbase, fullA[c]);

    for (int k = 0; k < NCHUNK; ++k) {
        const int s = k & (NSTG - 1);

        // producer: prefetch chunk k+3 into stage (k+3)&3
        const int kp = k + (NSTG - 1);
        if (kp < NCHUNK) {
            const int sp = kp & (NSTG - 1);
            if (kp >= NSTG)   // stage reused: wait for consumers of kp-4
                MBAR_WAIT(emptyA[sp], ((kp >> 2) + 1) & 1);
            issue_stage(smb, sp, kp, tid, mrow, jbase, fullA[sp]);
        }

        // consumer: wait chunk k, then LDSM + MMA
        MBAR_WAIT(fullA[s], (k >> 2) & 1);

        const uint32_t abase = smb + s * STAGE_BYTES;
        const uint32_t bbase = abase + STAGE_A;

        #pragma unroll
        for (int kt = 0; kt < 2; ++kt) {
            uint32_t aF[2][4];
            #pragma unroll
            for (int mt = 0; mt < 2; ++mt) {
                const uint32_t o = (uint32_t)((a_row0 + mt * 16) * 64 + kt * 32 + a_koff);
                LDSM4(aF[mt], abase + swz64(o));
            }
            uint32_t bF[4][4];
            #pragma unroll
            for (int nt2 = 0; nt2 < 4; ++nt2) {
                const uint32_t o = (uint32_t)((b_rowc + nt2 * 16) * 64 + kt * 32 + b_koff);
                LDSM4(bF[nt2], bbase + swz64(o));
            }
            #pragma unroll
            for (int mt = 0; mt < 2; ++mt)
                #pragma unroll
                for (int nt = 0; nt < 8; ++nt)
                    MMA16816H(hmast[mt][nt], aF[mt],
                              bF[nt >> 1][(nt & 1) * 2], bF[nt >> 1][(nt & 1) * 2 + 1]);
        }

        if (lane == 0) MBAR_ARRIVE(emptyA[s]);   // warp done with stage s
    }
    __syncthreads();   // all warps done -> pipeline smem reusable for staging

    // stage gates as f16x2: sg[r * SGS + hc], hc = tc/2 = g*16 + jj/2
    uint32_t* sg = (uint32_t*)dynsmem;
    {
        const int rl = lane >> 2;            // row within 8-row group
        const int hc0 = wn * 32 + (lane & 3);
        #pragma unroll
        for (int mt = 0; mt < 2; ++mt)
            #pragma unroll
            for (int nt = 0; nt < 8; ++nt) {
                const int r = wm * 32 + mt * 16 + rl;
                const int hc = hc0 + nt * 4;
                sg[r * SGS + hc]       = hmast[mt][nt][0];
                sg[(r + 8) * SGS + hc] = hmast[mt][nt][1];
            }
    }
    __syncthreads();

    // fused LSTM elementwise: 128 rows x 16 half2-cols, float2 I/O
    const float2* sb2 = (const float2*)sbias;
    #pragma unroll 4
    for (int it = 0; it < 8; ++it) {
        const int idx = it * 256 + tid;
        const int r  = idx >> 4;
        const int j2 = idx & 15;             // half2 col within the 32-col slice
        float2 gi = __half22float2(*(const __half2*)&sg[r * SGS +      j2]);
        float2 gf = __half22float2(*(const __half2*)&sg[r * SGS + 16 + j2]);
        float2 gg = __half22float2(*(const __half2*)&sg[r * SGS + 32 + j2]);
        float2 go = __half22float2(*(const __half2*)&sg[r * SGS + 48 + j2]);
        const float2 b0 = sb2[     j2], b1 = sb2[16 + j2];
        const float2 b2 = sb2[32 + j2], b3 = sb2[48 + j2];
        gi.x += b0.x; gi.y += b0.y;
        gf.x += b1.x; gf.y += b1.y;
        gg.x += b2.x; gg.y += b2.y;
        go.x += b3.x; go.y += b3.y;
        const size_t gp = (size_t)(mrow + r) * HID + jbase + 2 * j2;
        const float2 cv = *(const float2*)(c_in + gp);
        float2 cc, hn;
        cc.x = sigf(gf.x) * cv.x + sigf(gi.x) * tanhf_fast(gg.x);
        cc.y = sigf(gf.y) * cv.y + sigf(gi.y) * tanhf_fast(gg.y);
        hn.x = sigf(go.x) * tanhf_fast(cc.x);
        hn.y = sigf(go.y) * tanhf_fast(cc.y);
        *(float2*)(c_out + gp) = cc;
        *(float2*)(h_out + gp) = hn;
    }
}

// ---------------- host launcher ----------------

extern "C" void kernel_launch(void* const* d_in, const int* in_sizes, int n_in,
                              void* d_out, int out_size)
{
    (void)in_sizes; (void)n_in; (void)out_size;
    const float* x  = (const float*)d_in[0];
    const float* h  = (const float*)d_in[1];
    const float* c  = (const float*)d_in[2];
    const float* Wi = (const float*)d_in[3];
    const float* Wh = (const float*)d_in[4];
    const float* bi = (const float*)d_in[5];
    const float* bh = (const float*)d_in[6];
    float* hout = (float*)d_out;
    float* cout = hout + (size_t)BATCH * HID;

    // pass 1: single conversion kernel (xh + weights)
    {
        const size_t n = (size_t)(BATCH + 1024) * KDIM / 8;
        conv_all_kernel<<<(unsigned)((n + 255) / 256), 256>>>(x, h, Wi, Wh);
    }

    // pass 2: GEMM + LSTM. grid: 512 m-tiles x 8 jslices (adjacent bids
    // share A rows -> L2 dedup). 3 CTAs/SM, 24 warps/SM.
    cudaFuncSetAttribute(lstm_gemm_kernel,
                         cudaFuncAttributeMaxDynamicSharedMemorySize, DYN_SMEM);
    lstm_gemm_kernel<<<(BATCH / M_TILE) * 8, 256, DYN_SMEM>>>(c, bi, bh, hout, cout);
}